// round 12
// baseline (speedup 1.0000x reference)
#include <cuda_runtime.h>
#include <math.h>

#define TQ 256
#define BQ 1024
#define DQ 64
#define HQ 32

// Scratch (no runtime allocation allowed)
__device__ float g_xt[TQ * BQ * HQ];                  // conv output, [t][b][o]
__device__ __align__(16) float g_w0t[192 * 32];       // vec4 layout, see prep
__device__ __align__(16) float g_w1t[96 * 32];
__device__ __align__(16) float g_w2t[96 * 32];

__device__ __forceinline__ float rcp_(float x) {
    float r; asm("rcp.approx.f32 %0, %1;" : "=f"(r) : "f"(x)); return r;
}
__device__ __forceinline__ float sigm_(float x) {
    return rcp_(1.0f + __expf(-x));
}
__device__ __forceinline__ float tanh_(float x) {
    return 1.0f - 2.0f * rcp_(1.0f + __expf(2.0f * x));
}
__device__ __forceinline__ float sigmoid_acc(float x) {
    return 1.0f / (1.0f + expf(-x));
}
__device__ __forceinline__ void fma2_(unsigned long long& acc,
                                      unsigned long long a,
                                      unsigned long long b) {
    asm("fma.rn.f32x2 %0, %1, %2, %3;" : "=l"(acc) : "l"(a), "l"(b), "l"(acc));
}
__device__ __forceinline__ unsigned long long fma2v_(unsigned long long a,
                                                     unsigned long long b,
                                                     unsigned long long c) {
    unsigned long long r;
    asm("fma.rn.f32x2 %0, %1, %2, %3;" : "=l"(r) : "l"(a), "l"(b), "l"(c));
    return r;
}
__device__ __forceinline__ unsigned long long mul2v_(unsigned long long a,
                                                     unsigned long long b) {
    unsigned long long r;
    asm("mul.rn.f32x2 %0, %1, %2;" : "=l"(r) : "l"(a), "l"(b));
    return r;
}
__device__ __forceinline__ float unpack_add_(unsigned long long acc) {
    float lo, hi;
    asm("mov.b64 {%0, %1}, %2;" : "=f"(lo), "=f"(hi) : "l"(acc));
    return lo + hi;
}
__device__ __forceinline__ unsigned long long pack2_(float lo, float hi) {
    unsigned long long r;
    asm("mov.b64 %0, {%1, %2};" : "=l"(r) : "f"(lo), "f"(hi));
    return r;
}
__device__ __forceinline__ void unpack2_(unsigned long long v, float& lo, float& hi) {
    asm("mov.b64 {%0, %1}, %2;" : "=f"(lo), "=f"(hi) : "l"(v));
}

// ---------------------------------------------------------------------------
// Kernel 0: repack conv weights (unchanged).
// ---------------------------------------------------------------------------
__global__ void prep_kernel(const float* __restrict__ w0,
                            const float* __restrict__ w1,
                            const float* __restrict__ w2) {
    int i = threadIdx.x + blockIdx.x * 256;
    if (i < 6144) {
        int jj = i & 3, o = (i >> 2) & 31, kd4 = i >> 7;
        int k = kd4 >> 4, d4 = kd4 & 15;
        g_w0t[i] = w0[o * 192 + (4 * d4 + jj) * 3 + k];
    }
    if (i < 3072) {
        int jj = i & 3, o = (i >> 2) & 31, ki4 = i >> 7;
        int k = ki4 >> 3, i4 = ki4 & 7;
        g_w1t[i] = w1[o * 96 + (4 * i4 + jj) * 3 + k];
        g_w2t[i] = w2[o * 96 + (4 * i4 + jj) * 3 + k];
    }
}

// ---------------------------------------------------------------------------
// Generic conv row-group (unchanged).
// ---------------------------------------------------------------------------
template <int NR, int ND4>
__device__ __forceinline__ void conv_group(
    const ulonglong2* __restrict__ wp, const ulonglong2* sv,
    int base, int o, float bz, float* av) {
    unsigned long long acc[NR];
    #pragma unroll
    for (int r = 0; r < NR; r++) acc[r] = 0ull;
    #pragma unroll
    for (int d4 = 0; d4 < ND4; d4++) {
        ulonglong2 wk0 = __ldg(&wp[d4 * 32 + o]);
        ulonglong2 wk1 = __ldg(&wp[(ND4 + d4) * 32 + o]);
        ulonglong2 wk2 = __ldg(&wp[(2 * ND4 + d4) * 32 + o]);
        ulonglong2 rr[NR + 2];
        #pragma unroll
        for (int r = 0; r < NR + 2; r++) rr[r] = sv[(base + r) * ND4 + d4];
        #pragma unroll
        for (int r = 0; r < NR; r++) {
            fma2_(acc[r], wk0.x, rr[r].x);     fma2_(acc[r], wk0.y, rr[r].y);
            fma2_(acc[r], wk1.x, rr[r + 1].x); fma2_(acc[r], wk1.y, rr[r + 1].y);
            fma2_(acc[r], wk2.x, rr[r + 2].x); fma2_(acc[r], wk2.y, rr[r + 2].y);
        }
    }
    #pragma unroll
    for (int r = 0; r < NR; r++) av[r] = unpack_add_(acc[r]) + bz;
}

// ---------------------------------------------------------------------------
// Kernel 1: fused 3-layer TCN (R10 winning config: 128 thr, 4 blocks/SM).
// ---------------------------------------------------------------------------
__global__ __launch_bounds__(128, 4) void conv_fused_kernel(
    const float* __restrict__ x,
    const float* __restrict__ b0, const float* __restrict__ b1,
    const float* __restrict__ b2) {
    __shared__ __align__(16) float xs[70 * 64];
    __shared__ __align__(16) float s1[72 * 32];
    __shared__ __align__(16) float s2[68 * 32];
    const ulonglong2* xs2 = (const ulonglong2*)xs;
    const ulonglong2* s1v = (const ulonglong2*)s1;
    const ulonglong2* s2v = (const ulonglong2*)s2;

    const int tid = threadIdx.x;
    const int b = blockIdx.x >> 2;
    const int t0 = (blockIdx.x & 3) * 64;

    {
        float4* xs4f = (float4*)xs;
        const float4 zero4 = make_float4(0.f, 0.f, 0.f, 0.f);
        for (int i = tid; i < 70 * 16; i += 128) {
            int r = i >> 4, d4 = i & 15, t = t0 - 3 + r;
            xs4f[i] = (t >= 0 && t < TQ)
                ? __ldg((const float4*)(x + b * TQ * DQ + t * DQ + d4 * 4))
                : zero4;
        }
    }
    s1[68 * 32 + tid] = 0.0f;
    __syncthreads();

    const int w = tid >> 5, o = tid & 31;
    const ulonglong2* wp0 = (const ulonglong2*)g_w0t;
    const ulonglong2* wp1 = (const ulonglong2*)g_w1t;
    const ulonglong2* wp2 = (const ulonglong2*)g_w2t;

    const int rbase = 17 * w;

    {
        float bz = __ldg(&b0[o]);
        float av[17];
        conv_group<4, 16>(wp0, xs2, rbase, o, bz, av);
        conv_group<4, 16>(wp0, xs2, rbase + 4, o, bz, av + 4);
        conv_group<4, 16>(wp0, xs2, rbase + 8, o, bz, av + 8);
        conv_group<5, 16>(wp0, xs2, rbase + 12, o, bz, av + 12);
        #pragma unroll
        for (int r = 0; r < 17; r++) {
            int row = rbase + r, tt = t0 - 2 + row;
            float v = fmaxf(av[r], 0.0f);
            if (tt < 0 || tt >= TQ) v = 0.0f;
            s1[row * 32 + o] = v;
        }
    }
    __syncthreads();

    {
        float bz = __ldg(&b1[o]);
        float av[17];
        conv_group<4, 8>(wp1, s1v, rbase, o, bz, av);
        conv_group<4, 8>(wp1, s1v, rbase + 4, o, bz, av + 4);
        conv_group<4, 8>(wp1, s1v, rbase + 8, o, bz, av + 8);
        conv_group<5, 8>(wp1, s1v, rbase + 12, o, bz, av + 12);
        #pragma unroll
        for (int r = 0; r < 17; r++) {
            int row = rbase + r, tt = t0 - 1 + row;
            float v = fmaxf(av[r], 0.0f);
            if (tt < 0 || tt >= TQ) v = 0.0f;
            s2[row * 32 + o] = v;
        }
    }
    __syncthreads();

    {
        float bz = __ldg(&b2[o]);
        float av[16];
        conv_group<4, 8>(wp2, s2v, 16 * w, o, bz, av);
        conv_group<4, 8>(wp2, s2v, 16 * w + 4, o, bz, av + 4);
        conv_group<4, 8>(wp2, s2v, 16 * w + 8, o, bz, av + 8);
        conv_group<4, 8>(wp2, s2v, 16 * w + 12, o, bz, av + 12);
        #pragma unroll
        for (int r = 0; r < 16; r++) {
            const int t = t0 + 16 * w + r;
            g_xt[t * (BQ * HQ) + b * HQ + o] = fmaxf(av[r], 0.0f);
        }
    }
}

// ---------------------------------------------------------------------------
// Packed conjugated RY gate: amplitudes a0,a1 hold (re,im) as f32x2.
// a_new = gc2*a + gs2*shfl(a_partner). Same mul-then-fma rounding as scalar.
// ---------------------------------------------------------------------------
#define QGATE(MREG, LAM, G) do { \
    unsigned long long b0_ = (MREG) ? a1 : a0; \
    unsigned long long b1_ = (MREG) ? a0 : a1; \
    unsigned long long o0_ = __shfl_xor_sync(FULL, b0_, (LAM)); \
    unsigned long long o1_ = __shfl_xor_sync(FULL, b1_, (LAM)); \
    a0 = fma2v_(gs02[G], o0_, mul2v_(gc2[G], a0)); \
    a1 = fma2v_(gs12[G], o1_, mul2v_(gc2[G], a1)); \
} while (0)

// ---------------------------------------------------------------------------
// Kernel 2: merged recurrent scan t=0..255 (R7 structure + f32x2 packing).
// ---------------------------------------------------------------------------
__global__ __launch_bounds__(256, 1) void recurrent_kernel(
    const float* __restrict__ Wih, const float* __restrict__ Whh,
    const float* __restrict__ bih, const float* __restrict__ bhh,
    const float* __restrict__ qweights,
    const float* __restrict__ Wfc, const float* __restrict__ bfc,
    const float* __restrict__ Wout, const float* __restrict__ boutp,
    float* __restrict__ out) {
    __shared__ __align__(16) float xhf[2][256];     // [half][b*64 + idx]
    __shared__ float gsm[2][128 * 5];               // [half][j*5 + bb]
    __shared__ float qc[18], qs[18];

    const unsigned FULL = 0xffffffffu;
    const int tid = threadIdx.x;
    const int l = tid & 31;
    const int wrp = tid >> 5;
    const int half = tid >> 7;
    const int wb = wrp & 3;
    const int bglob = blockIdx.x * 8 + wrp;
    const int j = tid & 127;
    const int barid = half + 1;

    // ---- pack weight column j as adjacent-k pairs ----
    unsigned long long wpk[32];
    #pragma unroll
    for (int p = 0; p < 16; p++)
        wpk[p] = pack2_(Wih[j * 32 + 2 * p], Wih[j * 32 + 2 * p + 1]);
    #pragma unroll
    for (int p = 0; p < 16; p++)
        wpk[16 + p] = pack2_(Whh[j * 32 + 2 * p], Whh[j * 32 + 2 * p + 1]);
    const float biasj = bih[j] + bhh[j];

    if (tid < 18) {
        float a = 0.5f * qweights[tid];
        qc[tid] = cosf(a);
        qs[tid] = sinf(a);
    }

    const float wfc0 = Wfc[l * 6 + 0], wfc1 = Wfc[l * 6 + 1], wfc2 = Wfc[l * 6 + 2];
    const float wfc3 = Wfc[l * 6 + 3], wfc4 = Wfc[l * 6 + 4], wfc5 = Wfc[l * 6 + 5];
    const float bfcl = bfc[l];
    const float woutl = Wout[l];
    __syncthreads();   // qc/qs visible

    // ---- layer-1 RY coefficients (folded into kets) ----
    float c1q[6], s1q[6];
    #pragma unroll
    for (int q = 0; q < 6; q++) { c1q[q] = qc[q]; s1q[q] = qs[q]; }

    // ---- conjugated-gate coefficients, packed {v,v} ----
    const int PHI[12]  = {31, 16, 24, 28, 30, 31, 21, 15, 23, 11, 21, 10};
    const int GREG[12] = { 0,  1,  1,  1,  1,  1,  1,  1,  0,  1,  0,  1};
    unsigned long long gc2[12], gs02[12], gs12[12];
    #pragma unroll
    for (int g = 0; g < 12; g++) {
        const int idx = 6 + g;
        float cg = qc[idx], sg = qs[idx];
        int f0 = __popc(l & PHI[g]) & 1;
        float s0 = f0 ? sg : -sg;
        float s1 = (f0 ^ GREG[g]) ? sg : -sg;
        gc2[g] = pack2_(cg, cg);
        gs02[g] = pack2_(s0, s0);
        gs12[g] = pack2_(s1, s1);
    }
    // ---- WHT butterfly sign constants {±1,±1} per stage ----
    unsigned long long sgn2[5];
    #pragma unroll
    for (int bb = 0; bb < 5; bb++) {
        float s = (l & (1 << bb)) ? -1.0f : 1.0f;
        sgn2[bb] = pack2_(s, s);
    }

    float h = 0.0f, c = 0.0f;
    float xt = g_xt[bglob * HQ + l];

    for (int t = 0; t < TQ; t++) {
        // ---- stage activations batch-major: [b*64 + k] ----
        xhf[half][wb * 64 + l] = xt;
        xhf[half][wb * 64 + 32 + l] = h;
        asm volatile("bar.sync %0, 128;" :: "r"(barid) : "memory");

        float xt_next = 0.0f;
        if (t + 1 < TQ) xt_next = g_xt[(t + 1) * (BQ * HQ) + bglob * HQ + l];

        // ---- matvec ----
        {
            unsigned long long m0 = 0ull, m1 = 0ull, m2 = 0ull, m3 = 0ull;
            const ulonglong2* xv = (const ulonglong2*)&xhf[half][0];
            #pragma unroll
            for (int kg = 0; kg < 16; kg++) {
                ulonglong2 x0 = xv[kg];
                ulonglong2 x1 = xv[16 + kg];
                ulonglong2 x2 = xv[32 + kg];
                ulonglong2 x3 = xv[48 + kg];
                fma2_(m0, wpk[2 * kg], x0.x); fma2_(m0, wpk[2 * kg + 1], x0.y);
                fma2_(m1, wpk[2 * kg], x1.x); fma2_(m1, wpk[2 * kg + 1], x1.y);
                fma2_(m2, wpk[2 * kg], x2.x); fma2_(m2, wpk[2 * kg + 1], x2.y);
                fma2_(m3, wpk[2 * kg], x3.x); fma2_(m3, wpk[2 * kg + 1], x3.y);
            }
            gsm[half][j * 5 + 0] = unpack_add_(m0) + biasj;
            gsm[half][j * 5 + 1] = unpack_add_(m1) + biasj;
            gsm[half][j * 5 + 2] = unpack_add_(m2) + biasj;
            gsm[half][j * 5 + 3] = unpack_add_(m3) + biasj;
        }
        asm volatile("bar.sync %0, 128;" :: "r"(barid) : "memory");

        // ---- LSTM cell + chaotic maps ----
        float gi = gsm[half][l * 5 + wb];
        float gf = gsm[half][(l + 32) * 5 + wb];
        float gg = gsm[half][(l + 64) * 5 + wb];
        float go = gsm[half][(l + 96) * 5 + wb];
        c = sigm_(gf) * c + sigm_(gi) * tanh_(gg);
        h = sigm_(go) * tanh_(c);
        h = 3.99f * h * (1.0f - h);
        float x0h = __shfl_sync(FULL, h, 0);
        float y0h = __shfl_sync(FULL, h, 1);
        if (l == 0) h = 1.0f - 1.4f * (x0h * x0h) + y0h;
        if (l == 1) h = 0.3f * x0h;

        // ---- 6-qubit circuit ----
        float ang = (l < 6) ? 0.5f * h : 0.0f;
        float ssin, scos;
        __sincosf(ang, &ssin, &scos);
        float cs[6], sn[6];
        #pragma unroll
        for (int q = 0; q < 6; q++) {
            cs[q] = __shfl_sync(FULL, scos, q);
            sn[q] = __shfl_sync(FULL, ssin, q);
        }
        // kets psi_i = RY(layer1) * RZ * RY * RX |0>
        float p0r[6], p0i[6], p1r[6], p1i[6];
        #pragma unroll
        for (int i = 0; i < 6; i++) {
            const int i1 = (i + 1) % 6, i2 = (i + 2) % 6;
            float cx = cs[i], sx = sn[i];
            float cy = cs[i1], sy = sn[i1];
            float cz = cs[i2], sz = sn[i2];
            float ur = cy * cx, ui = sy * sx;
            float vr = sy * cx, vi = -(cy * sx);
            float q0r = ur * cz + ui * sz;
            float q0i = ui * cz - ur * sz;
            float q1r = vr * cz - vi * sz;
            float q1i = vi * cz + vr * sz;
            float cv = c1q[i], sv = s1q[i];
            p0r[i] = cv * q0r - sv * q1r;
            p0i[i] = cv * q0i - sv * q1i;
            p1r[i] = sv * q0r + cv * q1r;
            p1i[i] = sv * q0i + cv * q1i;
        }
        // product state: factor over qubits 1..5 (lane bits), split qubit 0
        float cr = 1.0f, cii = 0.0f;
        #pragma unroll
        for (int q = 1; q < 6; q++) {
            int bit = (l >> (5 - q)) & 1;
            float fr = bit ? p1r[q] : p0r[q];
            float fi = bit ? p1i[q] : p0i[q];
            float nr = cr * fr - cii * fi;
            float ni = cr * fi + cii * fr;
            cr = nr; cii = ni;
        }
        float a0r = cr * p0r[0] - cii * p0i[0];
        float a0i = cr * p0i[0] + cii * p0r[0];
        float a1r = cr * p1r[0] - cii * p1i[0];
        float a1i = cr * p1i[0] + cii * p1r[0];
        unsigned long long a0 = pack2_(a0r, a0i);
        unsigned long long a1 = pack2_(a1r, a1i);

        // ---- conjugated variational gates (packed f32x2) ----
        QGATE(1, 16, 0);  QGATE(0, 24, 1);  QGATE(0, 12, 2);
        QGATE(0, 6, 3);   QGATE(0, 3, 4);   QGATE(1, 17, 5);
        QGATE(1, 8, 6);   QGATE(0, 20, 7);  QGATE(0, 10, 8);
        QGATE(0, 5, 9);   QGATE(1, 18, 10); QGATE(0, 25, 11);

        // ---- dual WHT measurement (packed butterfly) ----
        unpack2_(a0, a0r, a0i);
        unpack2_(a1, a1r, a1i);
        float pp = a0r * a0r + a0i * a0i;
        float pq = a1r * a1r + a1i * a1i;
        unsigned long long uw = pack2_(pp + pq, pp - pq);   // (u, w)
        #pragma unroll
        for (int bb = 4; bb >= 0; bb--) {
            unsigned long long o = __shfl_xor_sync(FULL, uw, 1 << bb);
            uw = fma2v_(sgn2[bb], uw, o);    // (l&m)? o-uw : uw+o
        }
        float u, wv;
        unpack2_(uw, u, wv);
        float e0 = __shfl_sync(FULL, wv, 12);
        float e1 = __shfl_sync(FULL, u, 26);
        float e2 = __shfl_sync(FULL, u, 13);
        float e3 = __shfl_sync(FULL, wv, 6);
        float e4 = __shfl_sync(FULL, wv, 19);
        float e5 = __shfl_sync(FULL, u, 25);
        h = h + e0 * wfc0 + e1 * wfc1 + e2 * wfc2
              + e3 * wfc3 + e4 * wfc4 + e5 * wfc5 + bfcl;

        xt = xt_next;
    }

    // ---- output: sigmoid(h @ Wout.T + bout) ----
    float v = h * woutl;
    #pragma unroll
    for (int m = 16; m >= 1; m >>= 1) v += __shfl_xor_sync(FULL, v, m);
    if (l == 0) out[bglob] = sigmoid_acc(v + boutp[0]);
}

// ---------------------------------------------------------------------------
extern "C" void kernel_launch(void* const* d_in, const int* in_sizes, int n_in,
                              void* d_out, int out_size) {
    const float* x   = (const float*)d_in[0];
    const float* w0  = (const float*)d_in[1];
    const float* b0  = (const float*)d_in[2];
    const float* w1  = (const float*)d_in[3];
    const float* b1  = (const float*)d_in[4];
    const float* w2  = (const float*)d_in[5];
    const float* b2  = (const float*)d_in[6];
    const float* Wih = (const float*)d_in[7];
    const float* Whh = (const float*)d_in[8];
    const float* bih = (const float*)d_in[9];
    const float* bhh = (const float*)d_in[10];
    const float* qw  = (const float*)d_in[11];
    const float* Wfc = (const float*)d_in[12];
    const float* bfc = (const float*)d_in[13];
    const float* Wout = (const float*)d_in[14];
    const float* bout = (const float*)d_in[15];
    float* out = (float*)d_out;

    prep_kernel<<<24, 256>>>(w0, w1, w2);
    conv_fused_kernel<<<BQ * 4, 128>>>(x, b0, b1, b2);
    recurrent_kernel<<<BQ / 8, 256>>>(Wih, Whh, bih, bhh, qw, Wfc, bfc,
                                      Wout, bout, out);
}